// round 13
// baseline (speedup 1.0000x reference)
#include <cuda_runtime.h>
#include <cuda_bf16.h>

// LightConv1d: out[b,c,t] = sum_{k=0..6} softmax(w[h])[k] * x[b,c,t-6+k] + bias[h]
// h = c % 16. Shapes: x [8,1024,4096] f32, weight [16,1,7] f32, bias [16] f32.
//
// R6 champion per-thread structure (block-strided float4, warp-shuffle causal
// halo, lane 0-1 global patch, no SMEM/barriers/reg-forcing), but with FINER
// CTA GRANULARITY: 128-thread CTAs each covering HALF a row (grid 16384).
// Identical coalescing and instruction stream; halves the per-CTA work
// quantum -> shorter CTA tails and finer wave-boundary backfill. The mid-row
// boundary is handled by the existing lane-0/1 global-patch path (those lines
// are L1/L2-resident from the adjacent CTA/warp loads).

#define T_LEN 4096
#define HALF_T (T_LEN / 2)     // 2048 elements per CTA
#define KSZ   7
#define NROWS (8 * 1024)
#define NTHREADS 128
#define NSEG 4   // 128 threads * 4 segs * 4 floats = 2048 = half a row
#define FULLMASK 0xffffffffu

__global__ __launch_bounds__(NTHREADS)
void lightconv1d_kernel(const float* __restrict__ x,
                        const float* __restrict__ weight,
                        const float* __restrict__ bias,
                        float* __restrict__ out)
{
    const int row  = blockIdx.x >> 1;        // b*1024 + c
    const int half = blockIdx.x & 1;         // which half-row
    const int tid  = threadIdx.x;
    const int lane = tid & 31;

    // xr/orow point at the ROW start; offsets below are row-global so the
    // causal halo indexing (t0 - 6) is uniform across the half boundary.
    const float* __restrict__ xr = x + (size_t)row * T_LEN;
    float* __restrict__ orow     = out + (size_t)row * T_LEN;
    const int base = half * HALF_T;           // 0 or 2048

    // Front-batch the 4 coalesced main loads (MLP_p1 = 4), default caching.
    float4 v[NSEG];
    #pragma unroll
    for (int seg = 0; seg < NSEG; ++seg)
        v[seg] = reinterpret_cast<const float4*>(xr + base)[tid + NTHREADS * seg];

    // Softmax of the 7 shared weights for this head (L1-resident).
    const int h = row & 15;                   // c % 16
    float wk[KSZ];
    float mx = -1e30f;
    #pragma unroll
    for (int k = 0; k < KSZ; ++k) {
        wk[k] = __ldg(&weight[h * KSZ + k]);
        mx = fmaxf(mx, wk[k]);
    }
    float sum = 0.0f;
    #pragma unroll
    for (int k = 0; k < KSZ; ++k) {
        wk[k] = expf(wk[k] - mx);
        sum += wk[k];
    }
    const float inv = 1.0f / sum;
    #pragma unroll
    for (int k = 0; k < KSZ; ++k) wk[k] *= inv;
    const float bv = __ldg(&bias[h]);

    #pragma unroll
    for (int seg = 0; seg < NSEG; ++seg) {
        const int t0 = base + seg * (NTHREADS * 4) + tid * 4;   // row-global

        // win[i] = x[t0 - 6 + i], i = 0..9.
        float win[10];
        // Halo from neighbor lanes' registers:
        //   lane l-1 holds x[t0-4..t0-1], lane l-2 holds x[t0-8..t0-5].
        win[2] = __shfl_up_sync(FULLMASK, v[seg].x, 1);
        win[3] = __shfl_up_sync(FULLMASK, v[seg].y, 1);
        win[4] = __shfl_up_sync(FULLMASK, v[seg].z, 1);
        win[5] = __shfl_up_sync(FULLMASK, v[seg].w, 1);
        win[0] = __shfl_up_sync(FULLMASK, v[seg].z, 2);
        win[1] = __shfl_up_sync(FULLMASK, v[seg].w, 2);

        // Cross-warp (and mid-row) boundary lanes patch halo from global
        // (lines loaded by the adjacent warp/CTA -> L1/L2 hits).
        if (lane == 0) {
            if (t0 >= 8) {
                const float2 a = *reinterpret_cast<const float2*>(xr + t0 - 6);
                const float4 b = *reinterpret_cast<const float4*>(xr + t0 - 4);
                win[0] = a.x; win[1] = a.y;
                win[2] = b.x; win[3] = b.y; win[4] = b.z; win[5] = b.w;
            } else {
                // row start (half==0, seg==0, tid==0): causal zero padding.
                win[0] = win[1] = win[2] = win[3] = win[4] = win[5] = 0.0f;
            }
        } else if (lane == 1) {
            // delta-2 shuffle invalid for lane 1 only; win[2..5] are fine.
            if (t0 >= 8) {
                const float2 a = *reinterpret_cast<const float2*>(xr + t0 - 6);
                win[0] = a.x; win[1] = a.y;
            } else {
                win[0] = win[1] = 0.0f;
            }
        }

        win[6] = v[seg].x; win[7] = v[seg].y; win[8] = v[seg].z; win[9] = v[seg].w;

        float a0 = bv, a1 = bv, a2 = bv, a3 = bv;
        #pragma unroll
        for (int k = 0; k < KSZ; ++k) {
            a0 = fmaf(wk[k], win[k + 0], a0);
            a1 = fmaf(wk[k], win[k + 1], a1);
            a2 = fmaf(wk[k], win[k + 2], a2);
            a3 = fmaf(wk[k], win[k + 3], a3);
        }
        float4 r; r.x = a0; r.y = a1; r.z = a2; r.w = a3;
        reinterpret_cast<float4*>(orow + base)[tid + NTHREADS * seg] = r;
    }
}

extern "C" void kernel_launch(void* const* d_in, const int* in_sizes, int n_in,
                              void* d_out, int out_size)
{
    const float* x      = (const float*)d_in[0];
    const float* weight = (const float*)d_in[1];
    const float* bias   = (const float*)d_in[2];
    float* out          = (float*)d_out;

    lightconv1d_kernel<<<NROWS * 2, NTHREADS>>>(x, weight, bias, out);
}

// round 14
// speedup vs baseline: 1.0036x; 1.0036x over previous
#include <cuda_runtime.h>
#include <cuda_bf16.h>

// LightConv1d: out[b,c,t] = sum_{k=0..6} softmax(w[h])[k] * x[b,c,t-6+k] + bias[h]
// h = c % 16. Shapes: x [8,1024,4096] f32, weight [16,1,7] f32, bias [16] f32.
//
// FINAL (R6 champion; re-validated R10, R12): one CTA per row, 256 threads,
// 4 block-strided float4 segments per thread (perfect coalescing: 4 lines per
// LDG.128 warp instr). The 6-float causal halo comes from WARP SHUFFLES of
// neighbor lanes' registers (lane l-1 holds x[t0-4..t0-1], lane l-2 holds
// x[t0-6..t0-5]); only lanes 0-1 (cross-warp boundary) patch from global
// memory, hitting lines the previous warp just loaded (L1/L2-resident,
// DEFAULT caching — evict-first policies measurably break this). No SMEM,
// no barriers, no forced register cap.
//
// Measured: 36.9 us kernel = ~7.26 TB/s effective traffic (268 MB moved),
// ~91% of HBM spec for a 50:50 read/write stream — at the practical roofline.
// Exhaustively verified worse or neutral: SMEM staging (40.5), persistent
// grid (50.2), contiguous-16/thread (50.9), 512thr/forced-regs (39.1),
// 2 rows/CTA (38.9), 128-thr CTAs (37.2), __stcs stores (37.1),
// __ldcs loads (41.8).

#define T_LEN 4096
#define KSZ   7
#define NROWS (8 * 1024)
#define NTHREADS 256
#define NSEG 4   // 256 threads * 4 segs * 4 floats = 4096 = one full row
#define FULLMASK 0xffffffffu

__global__ __launch_bounds__(NTHREADS)
void lightconv1d_kernel(const float* __restrict__ x,
                        const float* __restrict__ weight,
                        const float* __restrict__ bias,
                        float* __restrict__ out)
{
    const int row  = blockIdx.x;         // b*1024 + c
    const int tid  = threadIdx.x;
    const int lane = tid & 31;

    const float* __restrict__ xr = x + (size_t)row * T_LEN;
    float* __restrict__ orow     = out + (size_t)row * T_LEN;

    // Front-batch the 4 coalesced main loads (MLP_p1 = 4), default caching.
    float4 v[NSEG];
    #pragma unroll
    for (int seg = 0; seg < NSEG; ++seg)
        v[seg] = reinterpret_cast<const float4*>(xr)[tid + NTHREADS * seg];

    // Softmax of the 7 shared weights for this head (L1-resident).
    const int h = row & 15;              // c % 16
    float wk[KSZ];
    float mx = -1e30f;
    #pragma unroll
    for (int k = 0; k < KSZ; ++k) {
        wk[k] = __ldg(&weight[h * KSZ + k]);
        mx = fmaxf(mx, wk[k]);
    }
    float sum = 0.0f;
    #pragma unroll
    for (int k = 0; k < KSZ; ++k) {
        wk[k] = expf(wk[k] - mx);
        sum += wk[k];
    }
    const float inv = 1.0f / sum;
    #pragma unroll
    for (int k = 0; k < KSZ; ++k) wk[k] *= inv;
    const float bv = __ldg(&bias[h]);

    #pragma unroll
    for (int seg = 0; seg < NSEG; ++seg) {
        const int t0 = seg * (NTHREADS * 4) + tid * 4;

        // win[i] = x[t0 - 6 + i], i = 0..9.
        float win[10];
        // Halo from neighbor lanes' registers:
        //   lane l-1 holds x[t0-4..t0-1], lane l-2 holds x[t0-8..t0-5].
        win[2] = __shfl_up_sync(FULLMASK, v[seg].x, 1);
        win[3] = __shfl_up_sync(FULLMASK, v[seg].y, 1);
        win[4] = __shfl_up_sync(FULLMASK, v[seg].z, 1);
        win[5] = __shfl_up_sync(FULLMASK, v[seg].w, 1);
        win[0] = __shfl_up_sync(FULLMASK, v[seg].z, 2);
        win[1] = __shfl_up_sync(FULLMASK, v[seg].w, 2);

        // Cross-warp boundary lanes patch their halo from global memory
        // (lines just loaded by the previous warp -> L1/L2 hits).
        if (lane == 0) {
            if (t0 >= 8) {
                const float2 a = *reinterpret_cast<const float2*>(xr + t0 - 6);
                const float4 b = *reinterpret_cast<const float4*>(xr + t0 - 4);
                win[0] = a.x; win[1] = a.y;
                win[2] = b.x; win[3] = b.y; win[4] = b.z; win[5] = b.w;
            } else {
                // tid==0, seg==0: causal zero padding.
                win[0] = win[1] = win[2] = win[3] = win[4] = win[5] = 0.0f;
            }
        } else if (lane == 1) {
            // delta-2 shuffle invalid for lane 1 only; win[2..5] are fine.
            if (t0 >= 8) {
                const float2 a = *reinterpret_cast<const float2*>(xr + t0 - 6);
                win[0] = a.x; win[1] = a.y;
            } else {
                // tid==1, seg==0: x[-2], x[-1] -> zeros.
                win[0] = win[1] = 0.0f;
            }
        }

        win[6] = v[seg].x; win[7] = v[seg].y; win[8] = v[seg].z; win[9] = v[seg].w;

        float a0 = bv, a1 = bv, a2 = bv, a3 = bv;
        #pragma unroll
        for (int k = 0; k < KSZ; ++k) {
            a0 = fmaf(wk[k], win[k + 0], a0);
            a1 = fmaf(wk[k], win[k + 1], a1);
            a2 = fmaf(wk[k], win[k + 2], a2);
            a3 = fmaf(wk[k], win[k + 3], a3);
        }
        float4 r; r.x = a0; r.y = a1; r.z = a2; r.w = a3;
        reinterpret_cast<float4*>(orow)[tid + NTHREADS * seg] = r;
    }
}

extern "C" void kernel_launch(void* const* d_in, const int* in_sizes, int n_in,
                              void* d_out, int out_size)
{
    const float* x      = (const float*)d_in[0];
    const float* weight = (const float*)d_in[1];
    const float* bias   = (const float*)d_in[2];
    float* out          = (float*)d_out;

    lightconv1d_kernel<<<NROWS, NTHREADS>>>(x, weight, bias, out);
}

// round 15
// speedup vs baseline: 1.0368x; 1.0331x over previous
#include <cuda_runtime.h>
#include <cuda_bf16.h>

// LightConv1d: out[b,c,t] = sum_{k=0..6} softmax(w[h])[k] * x[b,c,t-6+k] + bias[h]
// h = c % 16. Shapes: x [8,1024,4096] f32, weight [16,1,7] f32, bias [16] f32.
//
// R6 champion structure (one CTA per row, 256 threads, 4 block-strided float4
// segments, warp-shuffle causal halo, default caching, no SMEM/barriers/
// reg-forcing). This round's single delta: the lane-0/lane-1 halo patch is
// merged into ONE `lane < 2` branch with predicated selects (clamped loads +
// SEL zero-pad) instead of two BSSY/BSYNC pairs per segment — cuts branch/
// reconvergence overhead in a kernel at 57% issue utilization. Lane 1's
// win[2..5] keep the shuffle values via SEL; the extra float4 it loads is the
// same L1-resident line lane 0 loads (zero extra DRAM traffic).

#define T_LEN 4096
#define KSZ   7
#define NROWS (8 * 1024)
#define NTHREADS 256
#define NSEG 4   // 256 threads * 4 segs * 4 floats = 4096 = one full row
#define FULLMASK 0xffffffffu

__global__ __launch_bounds__(NTHREADS)
void lightconv1d_kernel(const float* __restrict__ x,
                        const float* __restrict__ weight,
                        const float* __restrict__ bias,
                        float* __restrict__ out)
{
    const int row  = blockIdx.x;         // b*1024 + c
    const int tid  = threadIdx.x;
    const int lane = tid & 31;

    const float* __restrict__ xr = x + (size_t)row * T_LEN;
    float* __restrict__ orow     = out + (size_t)row * T_LEN;

    // Front-batch the 4 coalesced main loads (MLP_p1 = 4), default caching.
    float4 v[NSEG];
    #pragma unroll
    for (int seg = 0; seg < NSEG; ++seg)
        v[seg] = reinterpret_cast<const float4*>(xr)[tid + NTHREADS * seg];

    // Softmax of the 7 shared weights for this head (L1-resident).
    const int h = row & 15;              // c % 16
    float wk[KSZ];
    float mx = -1e30f;
    #pragma unroll
    for (int k = 0; k < KSZ; ++k) {
        wk[k] = __ldg(&weight[h * KSZ + k]);
        mx = fmaxf(mx, wk[k]);
    }
    float sum = 0.0f;
    #pragma unroll
    for (int k = 0; k < KSZ; ++k) {
        wk[k] = expf(wk[k] - mx);
        sum += wk[k];
    }
    const float inv = 1.0f / sum;
    #pragma unroll
    for (int k = 0; k < KSZ; ++k) wk[k] *= inv;
    const float bv = __ldg(&bias[h]);

    #pragma unroll
    for (int seg = 0; seg < NSEG; ++seg) {
        const int t0 = seg * (NTHREADS * 4) + tid * 4;

        // win[i] = x[t0 - 6 + i], i = 0..9.
        float win[10];
        // Halo from neighbor lanes' registers:
        //   lane l-1 holds x[t0-4..t0-1], lane l-2 holds x[t0-8..t0-5].
        win[2] = __shfl_up_sync(FULLMASK, v[seg].x, 1);
        win[3] = __shfl_up_sync(FULLMASK, v[seg].y, 1);
        win[4] = __shfl_up_sync(FULLMASK, v[seg].z, 1);
        win[5] = __shfl_up_sync(FULLMASK, v[seg].w, 1);
        win[0] = __shfl_up_sync(FULLMASK, v[seg].z, 2);
        win[1] = __shfl_up_sync(FULLMASK, v[seg].w, 2);

        // Single-branch boundary patch for lanes 0-1 (cross-warp halo).
        // Clamped loads stay in-bounds; SEL applies the causal zero pad.
        // Lane 1 keeps its shuffle-derived win[2..5] (delta-1 from lane 0 is
        // valid); only lane 0 overwrites them from the loaded float4.
        if (lane < 2) {
            const int  hb = (t0 >= 8) ? t0 : 8;   // safe address base
            const bool ok = (t0 >= 8);
            const float2 a = *reinterpret_cast<const float2*>(xr + hb - 6);
            const float4 b = *reinterpret_cast<const float4*>(xr + hb - 4);
            win[0] = ok ? a.x : 0.0f;
            win[1] = ok ? a.y : 0.0f;
            const bool l0 = (lane == 0);
            win[2] = l0 ? (ok ? b.x : 0.0f) : win[2];
            win[3] = l0 ? (ok ? b.y : 0.0f) : win[3];
            win[4] = l0 ? (ok ? b.z : 0.0f) : win[4];
            win[5] = l0 ? (ok ? b.w : 0.0f) : win[5];
        }

        win[6] = v[seg].x; win[7] = v[seg].y; win[8] = v[seg].z; win[9] = v[seg].w;

        float a0 = bv, a1 = bv, a2 = bv, a3 = bv;
        #pragma unroll
        for (int k = 0; k < KSZ; ++k) {
            a0 = fmaf(wk[k], win[k + 0], a0);
            a1 = fmaf(wk[k], win[k + 1], a1);
            a2 = fmaf(wk[k], win[k + 2], a2);
            a3 = fmaf(wk[k], win[k + 3], a3);
        }
        float4 r; r.x = a0; r.y = a1; r.z = a2; r.w = a3;
        reinterpret_cast<float4*>(orow)[tid + NTHREADS * seg] = r;
    }
}

extern "C" void kernel_launch(void* const* d_in, const int* in_sizes, int n_in,
                              void* d_out, int out_size)
{
    const float* x      = (const float*)d_in[0];
    const float* weight = (const float*)d_in[1];
    const float* bias   = (const float*)d_in[2];
    float* out          = (float*)d_out;

    lightconv1d_kernel<<<NROWS, NTHREADS>>>(x, weight, bias, out);
}